// round 1
// baseline (speedup 1.0000x reference)
#include <cuda_runtime.h>
#include <cuda_fp16.h>

#define FD 16

// ---------------- channels-last half planes (scratch; no allocation allowed) ---------
__device__ __align__(16) __half g_xtyt0[2 * 16  * 128 * FD];   // [p][t][x][c]
__device__ __align__(16) __half g_xy0  [    128 * 128 * FD];   // [y][x][c]
__device__ __align__(16) __half g_xtyt1[2 * 32  * 256 * FD];
__device__ __align__(16) __half g_xy1  [    256 * 256 * FD];
__device__ __align__(16) __half g_xtyt2[2 * 64  * 512 * FD];
__device__ __align__(16) __half g_xy2  [    512 * 512 * FD];
__device__ __align__(16) __half g_w1t[32 * 48];  // [j][i]  (transposed w1, half)
__device__ float g_b1[32];
__device__ float g_w2[64];   // row-major (32,2)
__device__ float g_b2[2];

__device__ __forceinline__ __half* plane_ptr(int id) {
    switch (id) {
        case 0:  return g_xtyt0;
        case 1:  return g_xy0;
        case 2:  return g_xtyt1;
        case 3:  return g_xy1;
        case 4:  return g_xtyt2;
        default: return g_xy2;
    }
}

// (P, C, H, W) float  ->  [p][h][w][c] half
__global__ void transpose_kernel(const float* __restrict__ in, int id, int P, int H, int W) {
    __half* out = plane_ptr(id);
    int total = P * H * W * FD;
    for (int t = blockIdx.x * blockDim.x + threadIdx.x; t < total;
         t += gridDim.x * blockDim.x) {
        int c = t & (FD - 1);
        int rest = t >> 4;
        int w = rest % W; rest /= W;
        int h = rest % H;
        int p = rest / H;
        out[t] = __float2half_rn(in[((p * FD + c) * H + h) * W + w]);
    }
}

__global__ void prep_weights(const float* __restrict__ w1, const float* __restrict__ b1,
                             const float* __restrict__ w2, const float* __restrict__ b2) {
    int t = threadIdx.x;
    for (int idx = t; idx < 32 * 48; idx += blockDim.x) {
        int j = idx / 48, i = idx % 48;
        g_w1t[idx] = __float2half_rn(w1[i * 32 + j]);  // w1 is (48,32) row-major
    }
    if (t < 32) g_b1[t] = b1[t];
    if (t < 64) g_w2[t] = w2[t];
    if (t < 2)  g_b2[t] = b2[t];
}

// ---------------- main kernel -------------------------------------------------------

__device__ __forceinline__ void corner_acc(const __half* __restrict__ plane, int H, int W,
                                           int iy, int ix, float wgt, __half2* acc) {
    bool valid = ((unsigned)iy < (unsigned)H) && ((unsigned)ix < (unsigned)W);
    float wv = valid ? wgt : 0.0f;
    int cy = min(max(iy, 0), H - 1);
    int cx = min(max(ix, 0), W - 1);
    const uint4* p = reinterpret_cast<const uint4*>(plane + (cy * W + cx) * FD);
    uint4 a = __ldg(p);
    uint4 b = __ldg(p + 1);
    __half2 wh = __float2half2_rn(wv);
    const __half2* va = reinterpret_cast<const __half2*>(&a);
    const __half2* vb = reinterpret_cast<const __half2*>(&b);
#pragma unroll
    for (int k = 0; k < 4; k++) acc[k] = __hfma2(va[k], wh, acc[k]);
#pragma unroll
    for (int k = 0; k < 4; k++) acc[4 + k] = __hfma2(vb[k], wh, acc[4 + k]);
}

__device__ __forceinline__ void sample_plane16(const __half* __restrict__ plane, int H, int W,
                                               float gx, float gy, __half2* acc) {
    // align_corners=True mapping
    float x = (gx + 1.0f) * 0.5f * (float)(W - 1);
    float y = (gy + 1.0f) * 0.5f * (float)(H - 1);
    float xf = floorf(x), yf = floorf(y);
    float wx = x - xf, wy = y - yf;
    int ix0 = (int)xf, iy0 = (int)yf;
    corner_acc(plane, H, W, iy0,     ix0,     (1.0f - wx) * (1.0f - wy), acc);
    corner_acc(plane, H, W, iy0,     ix0 + 1, wx * (1.0f - wy),          acc);
    corner_acc(plane, H, W, iy0 + 1, ix0,     (1.0f - wx) * wy,          acc);
    corner_acc(plane, H, W, iy0 + 1, ix0 + 1, wx * wy,                   acc);
}

__global__ void __launch_bounds__(256)
triplane_kernel(const float* __restrict__ coords, float* __restrict__ out, int N) {
    __shared__ __align__(16) __half2 sw1t[32 * 24];  // [j][k] k over 24 half2 (48 in-dims)
    __shared__ float sb1[32], sw2[64], sb2[2];
    {
        const __half2* src = reinterpret_cast<const __half2*>(g_w1t);
        for (int t = threadIdx.x; t < 32 * 24; t += blockDim.x) sw1t[t] = src[t];
        if (threadIdx.x < 32) sb1[threadIdx.x] = g_b1[threadIdx.x];
        if (threadIdx.x < 64) sw2[threadIdx.x] = g_w2[threadIdx.x];
        if (threadIdx.x < 2)  sb2[threadIdx.x] = g_b2[threadIdx.x];
    }
    __syncthreads();

    int i = blockIdx.x * blockDim.x + threadIdx.x;
    if (i >= N) return;

    float cx = coords[3 * i + 0];
    float cy = coords[3 * i + 1];
    float ct = coords[3 * i + 2];

    __half2 acc[24];
#pragma unroll
    for (int k = 0; k < 24; k++) acc[k] = __float2half2_rn(0.0f);

    // level 0: rt=16, rx=128
    sample_plane16(g_xtyt0,                16,  128, cx, ct, acc + 0);   // f_xt
    sample_plane16(g_xtyt0 + 16 * 128 * FD, 16, 128, cy, ct, acc + 0);  // f_yt
    sample_plane16(g_xy0,                  128, 128, cx, cy, acc + 0);  // f_xy
    // level 1: rt=32, rx=256
    sample_plane16(g_xtyt1,                32,  256, cx, ct, acc + 8);
    sample_plane16(g_xtyt1 + 32 * 256 * FD, 32, 256, cy, ct, acc + 8);
    sample_plane16(g_xy1,                  256, 256, cx, cy, acc + 8);
    // level 2: rt=64, rx=512
    sample_plane16(g_xtyt2,                64,  512, cx, ct, acc + 16);
    sample_plane16(g_xtyt2 + 64 * 512 * FD, 64, 512, cy, ct, acc + 16);
    sample_plane16(g_xy2,                  512, 512, cx, cy, acc + 16);

    // MLP: 48 -> 32 (leaky relu) -> 2 (sigmoid), streamed (no h[] array)
    float z0 = sb2[0], z1 = sb2[1];
#pragma unroll 4
    for (int j = 0; j < 32; j++) {
        const __half2* wrow = sw1t + j * 24;
        __half2 s = __float2half2_rn(0.0f);
#pragma unroll
        for (int k = 0; k < 24; k++) s = __hfma2(acc[k], wrow[k], s);
        float hj = __low2float(s) + __high2float(s) + sb1[j];
        hj = hj > 0.0f ? hj : 0.01f * hj;
        z0 = fmaf(hj, sw2[2 * j + 0], z0);
        z1 = fmaf(hj, sw2[2 * j + 1], z1);
    }
    float2 o;
    o.x = 1.0f / (1.0f + __expf(-z0));
    o.y = 1.0f / (1.0f + __expf(-z1));
    reinterpret_cast<float2*>(out)[i] = o;
}

// ---------------- launch ------------------------------------------------------------
extern "C" void kernel_launch(void* const* d_in, const int* in_sizes, int n_in,
                              void* d_out, int out_size) {
    const float* coords = (const float*)d_in[0];
    const float* xtyt0  = (const float*)d_in[1];
    const float* xy0    = (const float*)d_in[2];
    const float* xtyt1  = (const float*)d_in[3];
    const float* xy1    = (const float*)d_in[4];
    const float* xtyt2  = (const float*)d_in[5];
    const float* xy2    = (const float*)d_in[6];
    const float* w1     = (const float*)d_in[7];
    const float* b1     = (const float*)d_in[8];
    const float* w2     = (const float*)d_in[9];
    const float* b2     = (const float*)d_in[10];
    int N = in_sizes[0] / 3;

    transpose_kernel<<<256,  256>>>(xtyt0, 0, 2, 16,  128);
    transpose_kernel<<<512,  256>>>(xy0,   1, 1, 128, 128);
    transpose_kernel<<<512,  256>>>(xtyt1, 2, 2, 32,  256);
    transpose_kernel<<<1024, 256>>>(xy1,   3, 1, 256, 256);
    transpose_kernel<<<1024, 256>>>(xtyt2, 4, 2, 64,  512);
    transpose_kernel<<<2048, 256>>>(xy2,   5, 1, 512, 512);
    prep_weights<<<1, 256>>>(w1, b1, w2, b2);

    int blocks = (N + 255) / 256;
    triplane_kernel<<<blocks, 256>>>(coords, (float*)d_out, N);
}

// round 4
// speedup vs baseline: 2.6161x; 2.6161x over previous
#include <cuda_runtime.h>
#include <cuda_fp16.h>

#define FD 16

// ---------------- channels-last half planes (scratch; no allocation allowed) --------
__device__ __align__(16) __half g_xtyt0[2 * 16  * 128 * FD];   // [p][t][x][c]
__device__ __align__(16) __half g_xy0  [    128 * 128 * FD];   // [y][x][c]
__device__ __align__(16) __half g_xtyt1[2 * 32  * 256 * FD];
__device__ __align__(16) __half g_xy1  [    256 * 256 * FD];
__device__ __align__(16) __half g_xtyt2[2 * 64  * 512 * FD];
__device__ __align__(16) __half g_xy2  [    512 * 512 * FD];
__device__ __align__(16) __half g_w1t[32 * 48];  // [j][i]  (transposed w1, half)
__device__ float g_b1[32];
__device__ float g_w2[64];   // row-major (32,2)
__device__ float g_b2[2];

__device__ __forceinline__ __half* plane_ptr(int id) {
    switch (id) {
        case 0:  return g_xtyt0;
        case 1:  return g_xy0;
        case 2:  return g_xtyt1;
        case 3:  return g_xy1;
        case 4:  return g_xtyt2;
        default: return g_xy2;
    }
}

// (P, C, H, W) float -> [p][h][w][c] half.  Thread = one (p,h,w); loops c.
// Reads: warp covers 32 consecutive w per c -> fully coalesced 128B.
// Writes: 32B contiguous per thread -> coalesced 1KB per warp.
__global__ void transpose_kernel(const float* __restrict__ in, int id, int P, int H, int W) {
    __half* out = plane_ptr(id);
    int total = P * H * W;
    size_t planeHW = (size_t)H * W;
    for (int t = blockIdx.x * blockDim.x + threadIdx.x; t < total;
         t += gridDim.x * blockDim.x) {
        int w = t % W;
        int rest = t / W;
        int h = rest % H;
        int p = rest / H;
        const float* src = in + ((size_t)p * FD * H + h) * W + w;
        __half tmp[16];
#pragma unroll
        for (int c = 0; c < 16; c++) tmp[c] = __float2half_rn(src[c * planeHW]);
        *reinterpret_cast<uint4*>(out + (size_t)t * 16)     = *reinterpret_cast<uint4*>(tmp);
        *reinterpret_cast<uint4*>(out + (size_t)t * 16 + 8) = *reinterpret_cast<uint4*>(tmp + 8);
    }
}

__global__ void prep_weights(const float* __restrict__ w1, const float* __restrict__ b1,
                             const float* __restrict__ w2, const float* __restrict__ b2) {
    int t = threadIdx.x;
    for (int idx = t; idx < 32 * 48; idx += blockDim.x) {
        int j = idx / 48, i = idx % 48;
        g_w1t[idx] = __float2half_rn(w1[i * 32 + j]);  // w1 is (48,32) row-major
    }
    if (t < 32) g_b1[t] = b1[t];
    if (t < 64) g_w2[t] = w2[t];
    if (t < 2)  g_b2[t] = b2[t];
}

// ---------------- main kernel -------------------------------------------------------

struct Ax { int s; float f; };

// align_corners=True; coords in [-1,1) so only edges need clamping:
// region columns/rows are (s, s+1), weight f = x - s in [0,1].
__device__ __forceinline__ Ax conv(float g, int R) {
    float x = (g + 1.0f) * 0.5f * (float)(R - 1);
    int s = (int)floorf(x);
    s = min(s, R - 2);
    s = max(s, 0);
    Ax a; a.s = s; a.f = x - (float)s; return a;
}

// One sample, quad-cooperative: lane chunk l8 = 8*(tid&3) halves into the 64B
// [x0 c0..15][x1 c0..15] row region.  wl is this lane's x-side weight.
__device__ __forceinline__ void samp(const __half* __restrict__ plane, int W,
                                     Ax X, Ax Y, float wl, int l8, __half2* acc) {
    const __half* p0 = plane + ((size_t)(Y.s * W + X.s) << 4) + l8;
    uint4 d0 = __ldg(reinterpret_cast<const uint4*>(p0));
    uint4 d1 = __ldg(reinterpret_cast<const uint4*>(p0 + W * FD));
    __half2 w0 = __float2half2_rn(wl * (1.0f - Y.f));
    __half2 w1 = __float2half2_rn(wl * Y.f);
    const __half2* a0 = reinterpret_cast<const __half2*>(&d0);
    const __half2* a1 = reinterpret_cast<const __half2*>(&d1);
#pragma unroll
    for (int j = 0; j < 4; j++) {
        acc[j] = __hfma2(a0[j], w0, acc[j]);
        acc[j] = __hfma2(a1[j], w1, acc[j]);
    }
}

template<int RX, int RT>
__device__ __forceinline__ void level(const __half* __restrict__ xtyt,
                                      const __half* __restrict__ xy,
                                      float cx, float cy, float ct,
                                      int xs, int l8, __half2* acc) {
    Ax u = conv(cx, RX);
    Ax v = conv(cy, RX);
    Ax w = conv(ct, RT);
    float fu = xs ? u.f : 1.0f - u.f;
    float fv = xs ? v.f : 1.0f - v.f;
    samp(xtyt,                RX, u, w, fu, l8, acc);   // f_xt  (x=cx, y=ct)
    samp(xtyt + RT * RX * FD, RX, v, w, fv, l8, acc);   // f_yt  (x=cy, y=ct)
    samp(xy,                  RX, u, v, fu, l8, acc);   // f_xy  (x=cx, y=cy)
}

__global__ void __launch_bounds__(256)
triplane_kernel(const float* __restrict__ coords, float2* __restrict__ out, int N) {
    __shared__ __align__(16) float  scoord[256 * 3];   // staged coords, coalesced
    __shared__ __align__(16) __half feats[256][56];    // 48 used, pad to 56
    __shared__ __align__(16) __half2 sw1t[32 * 24];
    __shared__ float sb1[32], sw2[64], sb2[2];
    {
        const __half2* src = reinterpret_cast<const __half2*>(g_w1t);
        for (int t = threadIdx.x; t < 32 * 24; t += 256) sw1t[t] = src[t];
        if (threadIdx.x < 32) sb1[threadIdx.x] = g_b1[threadIdx.x];
        if (threadIdx.x < 64) sw2[threadIdx.x] = g_w2[threadIdx.x];
        if (threadIdx.x < 2)  sb2[threadIdx.x] = g_b2[threadIdx.x];
    }

    int base = blockIdx.x * 256;
    // stage coords: 768 floats, coalesced; clamp tail block reads to N
    {
        int lim = min(3 * N - 3 * base, 768);
        const float* cp = coords + 3 * base;
        for (int t = threadIdx.x; t < 768; t += 256)
            scoord[t] = cp[min(t, lim - 1)];
    }
    __syncthreads();

    int l  = threadIdx.x & 3;   // quad lane: chunk of the 64B row region
    int xs = l >> 1;            // x-side (0 -> x0, 1 -> x1)
    int cb = l & 1;             // channel block (0 -> c0-7, 1 -> c8-15)
    int l8 = l * 8;

    // ---- gather phase: 4 lanes per point, 64 points per round, 4 rounds ----
#pragma unroll 1
    for (int r = 0; r < 4; r++) {
        int row = r * 64 + (threadIdx.x >> 2);
        int rc  = min(row, N - 1 - base);   // clamped (tail block only)
        float cx = scoord[3 * rc + 0];
        float cy = scoord[3 * rc + 1];
        float ct = scoord[3 * rc + 2];

        __half2 acc[12];
#pragma unroll
        for (int k = 0; k < 12; k++) acc[k] = __float2half2_rn(0.0f);

        level<128, 16>(g_xtyt0, g_xy0, cx, cy, ct, xs, l8, acc + 0);
        level<256, 32>(g_xtyt1, g_xy1, cx, cy, ct, xs, l8, acc + 4);
        level<512, 64>(g_xtyt2, g_xy2, cx, cy, ct, xs, l8, acc + 8);

        // combine x0/x1 partial sums across lane pairs (l ^ 2)
#pragma unroll
        for (int k = 0; k < 12; k++) {
            unsigned o = __shfl_xor_sync(0xFFFFFFFFu,
                                         *reinterpret_cast<unsigned*>(&acc[k]), 2);
            acc[k] = __hadd2(acc[k], *reinterpret_cast<__half2*>(&o));
        }

        if (l < 2) {
#pragma unroll
            for (int L = 0; L < 3; L++) {
                uint4 vv;
                vv.x = *reinterpret_cast<unsigned*>(&acc[4 * L + 0]);
                vv.y = *reinterpret_cast<unsigned*>(&acc[4 * L + 1]);
                vv.z = *reinterpret_cast<unsigned*>(&acc[4 * L + 2]);
                vv.w = *reinterpret_cast<unsigned*>(&acc[4 * L + 3]);
                *reinterpret_cast<uint4*>(&feats[row][L * 16 + 8 * cb]) = vv;
            }
        }
    }
    __syncthreads();

    // ---- MLP phase: 1 point per thread ----
    int pt = base + threadIdx.x;
    if (pt < N) {
        __half2 f[24];
        const uint4* fr = reinterpret_cast<const uint4*>(&feats[threadIdx.x][0]);
#pragma unroll
        for (int k = 0; k < 6; k++) {
            uint4 vv = fr[k];
            f[4 * k + 0] = *reinterpret_cast<__half2*>(&vv.x);
            f[4 * k + 1] = *reinterpret_cast<__half2*>(&vv.y);
            f[4 * k + 2] = *reinterpret_cast<__half2*>(&vv.z);
            f[4 * k + 3] = *reinterpret_cast<__half2*>(&vv.w);
        }
        float z0 = sb2[0], z1 = sb2[1];
#pragma unroll 4
        for (int j = 0; j < 32; j++) {
            const __half2* wr = sw1t + j * 24;
            __half2 sa = __hmul2(f[0], wr[0]);
            __half2 sb = __hmul2(f[1], wr[1]);
#pragma unroll
            for (int k = 2; k < 24; k += 2) {
                sa = __hfma2(f[k],     wr[k],     sa);
                sb = __hfma2(f[k + 1], wr[k + 1], sb);
            }
            sa = __hadd2(sa, sb);
            float hj = __low2float(sa) + __high2float(sa) + sb1[j];
            hj = hj > 0.0f ? hj : 0.01f * hj;
            z0 = fmaf(hj, sw2[2 * j + 0], z0);
            z1 = fmaf(hj, sw2[2 * j + 1], z1);
        }
        float2 o;
        o.x = 1.0f / (1.0f + __expf(-z0));
        o.y = 1.0f / (1.0f + __expf(-z1));
        out[pt] = o;
    }
}

// ---------------- launch ------------------------------------------------------------
extern "C" void kernel_launch(void* const* d_in, const int* in_sizes, int n_in,
                              void* d_out, int out_size) {
    const float* coords = (const float*)d_in[0];
    const float* xtyt0  = (const float*)d_in[1];
    const float* xy0    = (const float*)d_in[2];
    const float* xtyt1  = (const float*)d_in[3];
    const float* xy1    = (const float*)d_in[4];
    const float* xtyt2  = (const float*)d_in[5];
    const float* xy2    = (const float*)d_in[6];
    const float* w1     = (const float*)d_in[7];
    const float* b1     = (const float*)d_in[8];
    const float* w2     = (const float*)d_in[9];
    const float* b2     = (const float*)d_in[10];
    int N = in_sizes[0] / 3;

    transpose_kernel<<<16,   256>>>(xtyt0, 0, 2, 16,  128);
    transpose_kernel<<<64,   256>>>(xy0,   1, 1, 128, 128);
    transpose_kernel<<<64,   256>>>(xtyt1, 2, 2, 32,  256);
    transpose_kernel<<<256,  256>>>(xy1,   3, 1, 256, 256);
    transpose_kernel<<<256,  256>>>(xtyt2, 4, 2, 64,  512);
    transpose_kernel<<<1024, 256>>>(xy2,   5, 1, 512, 512);
    prep_weights<<<1, 256>>>(w1, b1, w2, b2);

    int blocks = (N + 255) / 256;
    triplane_kernel<<<blocks, 256>>>(coords, (float2*)d_out, N);
}